// round 13
// baseline (speedup 1.0000x reference)
#include <cuda_runtime.h>

#define NPTS 1024
#define WEIGHT_THRESH 0.5f
#define EPS_W 1e-5f
#define RED_BLOCKS 444   // 3 resident blocks per SM on 148 SMs
#define MAX_ITERS 16     // >= ceil(4096/444)+1 = 10 with margin

// ---------------------------------------------------------------------------
// One 3x3 proper SVD (Jacobi on H^T H) -> R, t for batch `myb`.
// ---------------------------------------------------------------------------
__device__ __forceinline__ void svd_one(const float* __restrict__ tot,
                                        int myb,
                                        float* __restrict__ Rout,
                                        float* __restrict__ tout)
{
    float W  = tot[0];
    float d  = W + EPS_W;
    float id = __fdividef(1.0f, d);
    float coef = (2.0f * d - W) * id * id * id;

    float Sx[3] = {tot[1], tot[2], tot[3]};
    float Sy[3] = {tot[4], tot[5], tot[6]};
    float H[3][3];
    #pragma unroll
    for (int i = 0; i < 3; i++)
        #pragma unroll
        for (int j = 0; j < 3; j++)
            H[i][j] = tot[7 + i * 3 + j] * id - Sx[i] * Sy[j] * coef;

    float src_c[3] = {Sx[0] * id, Sx[1] * id, Sx[2] * id};
    float tgt_c[3] = {Sy[0] * id, Sy[1] * id, Sy[2] * id};

    // A = H^T H
    float A[3][3];
    #pragma unroll
    for (int i = 0; i < 3; i++)
        #pragma unroll
        for (int j = 0; j < 3; j++) {
            float s = 0.0f;
            #pragma unroll
            for (int k = 0; k < 3; k++) s += H[k][i] * H[k][j];
            A[i][j] = s;
        }

    float V[3][3] = {{1, 0, 0}, {0, 1, 0}, {0, 0, 1}};

    #pragma unroll 1
    for (int sweep = 0; sweep < 4; sweep++) {
        #pragma unroll
        for (int pair = 0; pair < 3; pair++) {
            const int p2 = (pair == 2) ? 1 : 0;
            const int q2 = (pair == 0) ? 1 : 2;
            float apq = A[p2][q2];
            if (fabsf(apq) > 1e-30f) {
                float tau = __fdividef(A[q2][q2] - A[p2][p2], 2.0f * apq);
                tau = fminf(fmaxf(tau, -1e18f), 1e18f);   // overflow-safe
                float h   = 1.0f + tau * tau;
                float sq  = h * rsqrtf(h);                // sqrt(1+tau^2)
                float tt  = __fdividef(copysignf(1.0f, tau),
                                       fabsf(tau) + sq);
                float cc  = rsqrtf(1.0f + tt * tt);
                float ss  = tt * cc;
                #pragma unroll
                for (int k = 0; k < 3; k++) {
                    float akp = A[k][p2], akq = A[k][q2];
                    A[k][p2] = cc * akp - ss * akq;
                    A[k][q2] = ss * akp + cc * akq;
                }
                #pragma unroll
                for (int k = 0; k < 3; k++) {
                    float apk = A[p2][k], aqk = A[q2][k];
                    A[p2][k] = cc * apk - ss * aqk;
                    A[q2][k] = ss * apk + cc * aqk;
                }
                #pragma unroll
                for (int k = 0; k < 3; k++) {
                    float vkp = V[k][p2], vkq = V[k][q2];
                    V[k][p2] = cc * vkp - ss * vkq;
                    V[k][q2] = ss * vkp + cc * vkq;
                }
            }
        }
    }

    float eig[3] = {A[0][0], A[1][1], A[2][2]};
    int i0 = 0, i1 = 1, i2 = 2, tmpi;
    if (eig[i0] < eig[i1]) { tmpi = i0; i0 = i1; i1 = tmpi; }
    if (eig[i0] < eig[i2]) { tmpi = i0; i0 = i2; i2 = tmpi; }
    if (eig[i1] < eig[i2]) { tmpi = i1; i1 = i2; i2 = tmpi; }

    float v0[3] = {V[0][i0], V[1][i0], V[2][i0]};
    float v1[3] = {V[0][i1], V[1][i1], V[2][i1]};
    float v2[3] = {v0[1] * v1[2] - v0[2] * v1[1],
                   v0[2] * v1[0] - v0[0] * v1[2],
                   v0[0] * v1[1] - v0[1] * v1[0]};

    float u0[3], u1[3], u2[3];
    #pragma unroll
    for (int i = 0; i < 3; i++)
        u0[i] = H[i][0] * v0[0] + H[i][1] * v0[1] + H[i][2] * v0[2];
    float rn0 = rsqrtf(u0[0] * u0[0] + u0[1] * u0[1] + u0[2] * u0[2] + 1e-30f);
    u0[0] *= rn0; u0[1] *= rn0; u0[2] *= rn0;

    #pragma unroll
    for (int i = 0; i < 3; i++)
        u1[i] = H[i][0] * v1[0] + H[i][1] * v1[1] + H[i][2] * v1[2];
    float dp = u1[0] * u0[0] + u1[1] * u0[1] + u1[2] * u0[2];
    u1[0] -= dp * u0[0]; u1[1] -= dp * u0[1]; u1[2] -= dp * u0[2];
    float rn1 = rsqrtf(u1[0] * u1[0] + u1[1] * u1[1] + u1[2] * u1[2] + 1e-30f);
    u1[0] *= rn1; u1[1] *= rn1; u1[2] *= rn1;

    u2[0] = u0[1] * u1[2] - u0[2] * u1[1];
    u2[1] = u0[2] * u1[0] - u0[0] * u1[2];
    u2[2] = u0[0] * u1[1] - u0[1] * u1[0];

    // R = V * U^T
    float R[3][3];
    #pragma unroll
    for (int i = 0; i < 3; i++)
        #pragma unroll
        for (int j = 0; j < 3; j++)
            R[i][j] = v0[i] * u0[j] + v1[i] * u1[j] + v2[i] * u2[j];

    float t[3];
    #pragma unroll
    for (int i = 0; i < 3; i++)
        t[i] = tgt_c[i] - (R[i][0] * src_c[0] + R[i][1] * src_c[1] + R[i][2] * src_c[2]);

    float* Rb = Rout + (size_t)myb * 9;
    #pragma unroll
    for (int i = 0; i < 3; i++)
        #pragma unroll
        for (int j = 0; j < 3; j++)
            Rb[i * 3 + j] = R[i][j];
    float* tb = tout + (size_t)myb * 3;
    tb[0] = t[0]; tb[1] = t[1]; tb[2] = t[2];
}

// ---------------------------------------------------------------------------
// Fused persistent kernel, contiguous batch ranges, register prefetch,
// reduce-scatter butterfly. SVD of batch it-1 is computed by one rotating
// lane DURING iteration it, hidden behind the memory period; only the final
// batch's SVD remains as tail.
// ---------------------------------------------------------------------------
__global__ __launch_bounds__(256, 3)
void wproc_fused(const float* __restrict__ src,
                 const float* __restrict__ tgt,
                 const float* __restrict__ wgt,
                 float* __restrict__ Rout,
                 float* __restrict__ tout,
                 int B)
{
    const int tid  = threadIdx.x;
    const int warp = tid >> 5, lane = tid & 31;

    // contiguous partition: first `rem` blocks get base+1 batches
    const int grid  = gridDim.x;
    const int base  = B / grid;
    const int rem   = B - base * grid;
    const int cnt   = base + (blockIdx.x < rem ? 1 : 0);
    const int start = blockIdx.x * base + min((int)blockIdx.x, rem);

    __shared__ float sm[2][8 * 16];
    __shared__ float svd_sm[MAX_ITERS][16];

    if (cnt > 0) {
        int b = start;

        float4 wv, a0, a1, a2, c0, c1, c2;
        {
            const float4* s4 = (const float4*)(src + (size_t)b * NPTS * 3);
            const float4* t4 = (const float4*)(tgt + (size_t)b * NPTS * 3);
            const float4* w4 = (const float4*)(wgt + (size_t)b * NPTS);
            wv = __ldcs(w4 + tid);
            a0 = __ldcs(s4 + 3 * tid + 0);
            a1 = __ldcs(s4 + 3 * tid + 1);
            a2 = __ldcs(s4 + 3 * tid + 2);
            c0 = __ldcs(t4 + 3 * tid + 0);
            c1 = __ldcs(t4 + 3 * tid + 1);
            c2 = __ldcs(t4 + 3 * tid + 2);
        }

        int p = 0;
        int it = 0;
        while (true) {
            const int bn = b + 1;
            const bool has_next = (it + 1 < cnt);

            // Prefetch next (sequential) batch while reducing current
            float4 nwv, na0, na1, na2, nc0, nc1, nc2;
            if (has_next) {
                const float4* s4 = (const float4*)(src + (size_t)bn * NPTS * 3);
                const float4* t4 = (const float4*)(tgt + (size_t)bn * NPTS * 3);
                const float4* w4 = (const float4*)(wgt + (size_t)bn * NPTS);
                nwv = __ldcs(w4 + tid);
                na0 = __ldcs(s4 + 3 * tid + 0);
                na1 = __ldcs(s4 + 3 * tid + 1);
                na2 = __ldcs(s4 + 3 * tid + 2);
                nc0 = __ldcs(t4 + 3 * tid + 0);
                nc1 = __ldcs(t4 + 3 * tid + 1);
                nc2 = __ldcs(t4 + 3 * tid + 2);
            }

            float ws[4];
            ws[0] = (wv.x < WEIGHT_THRESH) ? 0.0f : wv.x;
            ws[1] = (wv.y < WEIGHT_THRESH) ? 0.0f : wv.y;
            ws[2] = (wv.z < WEIGHT_THRESH) ? 0.0f : wv.z;
            ws[3] = (wv.w < WEIGHT_THRESH) ? 0.0f : wv.w;

            float px[4][3] = {{a0.x, a0.y, a0.z},
                              {a0.w, a1.x, a1.y},
                              {a1.z, a1.w, a2.x},
                              {a2.y, a2.z, a2.w}};
            float py[4][3] = {{c0.x, c0.y, c0.z},
                              {c0.w, c1.x, c1.y},
                              {c1.z, c1.w, c2.x},
                              {c2.y, c2.z, c2.w}};

            float acc[16];
            #pragma unroll
            for (int k = 0; k < 16; k++) acc[k] = 0.0f;

            #pragma unroll
            for (int k = 0; k < 4; k++) {
                float w = ws[k];
                float x0 = px[k][0], x1 = px[k][1], x2 = px[k][2];
                float y0 = py[k][0], y1 = py[k][1], y2 = py[k][2];
                acc[0] += w;
                acc[1] += w * x0;  acc[2] += w * x1;  acc[3] += w * x2;
                float wy0 = w * y0, wy1 = w * y1, wy2 = w * y2;
                acc[4] += wy0;     acc[5] += wy1;     acc[6] += wy2;
                acc[7]  += x0 * wy0;  acc[8]  += x0 * wy1;  acc[9]  += x0 * wy2;
                acc[10] += x1 * wy0;  acc[11] += x1 * wy1;  acc[12] += x1 * wy2;
                acc[13] += x2 * wy0;  acc[14] += x2 * wy1;  acc[15] += x2 * wy2;
            }

            // ---- reduce-scatter butterfly ----
            {
                bool hi = (lane & 16) != 0;
                #pragma unroll
                for (int j = 0; j < 8; j++) {
                    float send = hi ? acc[j] : acc[j + 8];
                    float keep = hi ? acc[j + 8] : acc[j];
                    acc[j] = keep + __shfl_xor_sync(0xffffffffu, send, 16);
                }
            }
            {
                bool hi = (lane & 8) != 0;
                #pragma unroll
                for (int j = 0; j < 4; j++) {
                    float send = hi ? acc[j] : acc[j + 4];
                    float keep = hi ? acc[j + 4] : acc[j];
                    acc[j] = keep + __shfl_xor_sync(0xffffffffu, send, 8);
                }
            }
            {
                bool hi = (lane & 4) != 0;
                #pragma unroll
                for (int j = 0; j < 2; j++) {
                    float send = hi ? acc[j] : acc[j + 2];
                    float keep = hi ? acc[j + 2] : acc[j];
                    acc[j] = keep + __shfl_xor_sync(0xffffffffu, send, 4);
                }
            }
            {
                bool hi = (lane & 2) != 0;
                float send = hi ? acc[0] : acc[1];
                float keep = hi ? acc[1] : acc[0];
                acc[0] = keep + __shfl_xor_sync(0xffffffffu, send, 2);
            }
            acc[0] += __shfl_xor_sync(0xffffffffu, acc[0], 1);

            const int accIdx = (lane >> 1) & 15;
            if ((lane & 1) == 0)
                sm[p][warp * 16 + accIdx] = acc[0];
            __syncthreads();
            if (tid < 16) {
                float s = 0.0f;
                #pragma unroll
                for (int w = 0; w < 8; w++) s += sm[p][w * 16 + tid];
                svd_sm[it][tid] = s;
            }

            // Hidden SVD: batch it-1's totals (written last iteration, fenced
            // by the barrier above) processed by one rotating non-warp-0 lane
            // while the block sits in this iteration's memory shadow.
            if (it > 0) {
                const int wsvd = 1 + ((it - 1) % 7);
                if (warp == wsvd && lane == 0)
                    svd_one(svd_sm[it - 1], start + it - 1, Rout, tout);
            }

            if (!has_next) break;
            wv = nwv; a0 = na0; a1 = na1; a2 = na2; c0 = nc0; c1 = nc1; c2 = nc2;
            b = bn;
            it++;
            p ^= 1;   // double-buffered smem: no second barrier needed
        }
    }

    // ---------------- tail: only the final batch's SVD ---------------------
    __syncthreads();
    if (tid == 0 && cnt > 0)
        svd_one(svd_sm[cnt - 1], start + cnt - 1, Rout, tout);
}

extern "C" void kernel_launch(void* const* d_in, const int* in_sizes, int n_in,
                              void* d_out, int out_size)
{
    const float* src = (const float*)d_in[0];
    const float* tgt = (const float*)d_in[1];
    const float* w   = (const float*)d_in[2];
    int B = in_sizes[2] / NPTS;
    float* Rout = (float*)d_out;
    float* tout = Rout + (size_t)B * 9;
    int grid = (B < RED_BLOCKS) ? B : RED_BLOCKS;
    wproc_fused<<<grid, 256>>>(src, tgt, w, Rout, tout, B);
}

// round 14
// speedup vs baseline: 1.4735x; 1.4735x over previous
#include <cuda_runtime.h>

#define NPTS 1024
#define WEIGHT_THRESH 0.5f
#define EPS_W 1e-5f
#define RED_BLOCKS 444   // 3 resident blocks per SM on 148 SMs
#define MAX_ITERS 16     // >= ceil(4096/444)+1 = 10 with margin

// ---------------------------------------------------------------------------
// Fused persistent kernel, contiguous batch ranges per block, register
// prefetch + reduce-scatter butterfly; parallel SIMT SVD tail (one warp-0
// lane per processed batch). This is the converged best structure.
// ---------------------------------------------------------------------------
__global__ __launch_bounds__(256, 3)
void wproc_fused(const float* __restrict__ src,
                 const float* __restrict__ tgt,
                 const float* __restrict__ wgt,
                 float* __restrict__ Rout,
                 float* __restrict__ tout,
                 int B)
{
    const int tid  = threadIdx.x;
    const int warp = tid >> 5, lane = tid & 31;

    // contiguous partition: first `rem` blocks get base+1 batches
    const int grid  = gridDim.x;
    const int base  = B / grid;
    const int rem   = B - base * grid;
    const int cnt   = base + (blockIdx.x < rem ? 1 : 0);
    const int start = blockIdx.x * base + min((int)blockIdx.x, rem);

    __shared__ float sm[2][8 * 16];
    __shared__ float svd_sm[MAX_ITERS][16];

    if (cnt > 0) {
        int b = start;

        float4 wv, a0, a1, a2, c0, c1, c2;
        {
            const float4* s4 = (const float4*)(src + (size_t)b * NPTS * 3);
            const float4* t4 = (const float4*)(tgt + (size_t)b * NPTS * 3);
            const float4* w4 = (const float4*)(wgt + (size_t)b * NPTS);
            wv = w4[tid];
            a0 = s4[3 * tid + 0]; a1 = s4[3 * tid + 1]; a2 = s4[3 * tid + 2];
            c0 = t4[3 * tid + 0]; c1 = t4[3 * tid + 1]; c2 = t4[3 * tid + 2];
        }

        int p = 0;
        int it = 0;
        while (true) {
            const int bn = b + 1;
            const bool has_next = (it + 1 < cnt);

            // Prefetch next (sequential) batch while reducing current
            float4 nwv, na0, na1, na2, nc0, nc1, nc2;
            if (has_next) {
                const float4* s4 = (const float4*)(src + (size_t)bn * NPTS * 3);
                const float4* t4 = (const float4*)(tgt + (size_t)bn * NPTS * 3);
                const float4* w4 = (const float4*)(wgt + (size_t)bn * NPTS);
                nwv = w4[tid];
                na0 = s4[3 * tid + 0]; na1 = s4[3 * tid + 1]; na2 = s4[3 * tid + 2];
                nc0 = t4[3 * tid + 0]; nc1 = t4[3 * tid + 1]; nc2 = t4[3 * tid + 2];
            }

            float ws[4];
            ws[0] = (wv.x < WEIGHT_THRESH) ? 0.0f : wv.x;
            ws[1] = (wv.y < WEIGHT_THRESH) ? 0.0f : wv.y;
            ws[2] = (wv.z < WEIGHT_THRESH) ? 0.0f : wv.z;
            ws[3] = (wv.w < WEIGHT_THRESH) ? 0.0f : wv.w;

            float px[4][3] = {{a0.x, a0.y, a0.z},
                              {a0.w, a1.x, a1.y},
                              {a1.z, a1.w, a2.x},
                              {a2.y, a2.z, a2.w}};
            float py[4][3] = {{c0.x, c0.y, c0.z},
                              {c0.w, c1.x, c1.y},
                              {c1.z, c1.w, c2.x},
                              {c2.y, c2.z, c2.w}};

            float acc[16];
            #pragma unroll
            for (int k = 0; k < 16; k++) acc[k] = 0.0f;

            #pragma unroll
            for (int k = 0; k < 4; k++) {
                float w = ws[k];
                float x0 = px[k][0], x1 = px[k][1], x2 = px[k][2];
                float y0 = py[k][0], y1 = py[k][1], y2 = py[k][2];
                acc[0] += w;
                acc[1] += w * x0;  acc[2] += w * x1;  acc[3] += w * x2;
                float wy0 = w * y0, wy1 = w * y1, wy2 = w * y2;
                acc[4] += wy0;     acc[5] += wy1;     acc[6] += wy2;
                acc[7]  += x0 * wy0;  acc[8]  += x0 * wy1;  acc[9]  += x0 * wy2;
                acc[10] += x1 * wy0;  acc[11] += x1 * wy1;  acc[12] += x1 * wy2;
                acc[13] += x2 * wy0;  acc[14] += x2 * wy1;  acc[15] += x2 * wy2;
            }

            // ---- reduce-scatter butterfly ----
            {
                bool hi = (lane & 16) != 0;
                #pragma unroll
                for (int j = 0; j < 8; j++) {
                    float send = hi ? acc[j] : acc[j + 8];
                    float keep = hi ? acc[j + 8] : acc[j];
                    acc[j] = keep + __shfl_xor_sync(0xffffffffu, send, 16);
                }
            }
            {
                bool hi = (lane & 8) != 0;
                #pragma unroll
                for (int j = 0; j < 4; j++) {
                    float send = hi ? acc[j] : acc[j + 4];
                    float keep = hi ? acc[j + 4] : acc[j];
                    acc[j] = keep + __shfl_xor_sync(0xffffffffu, send, 8);
                }
            }
            {
                bool hi = (lane & 4) != 0;
                #pragma unroll
                for (int j = 0; j < 2; j++) {
                    float send = hi ? acc[j] : acc[j + 2];
                    float keep = hi ? acc[j + 2] : acc[j];
                    acc[j] = keep + __shfl_xor_sync(0xffffffffu, send, 4);
                }
            }
            {
                bool hi = (lane & 2) != 0;
                float send = hi ? acc[0] : acc[1];
                float keep = hi ? acc[1] : acc[0];
                acc[0] = keep + __shfl_xor_sync(0xffffffffu, send, 2);
            }
            acc[0] += __shfl_xor_sync(0xffffffffu, acc[0], 1);

            const int accIdx = (lane >> 1) & 15;
            if ((lane & 1) == 0)
                sm[p][warp * 16 + accIdx] = acc[0];
            __syncthreads();
            if (tid < 16) {
                float s = 0.0f;
                #pragma unroll
                for (int w = 0; w < 8; w++) s += sm[p][w * 16 + tid];
                svd_sm[it][tid] = s;
            }

            if (!has_next) break;
            wv = nwv; a0 = na0; a1 = na1; a2 = na2; c0 = nc0; c1 = nc1; c2 = nc2;
            b = bn;
            it++;
            p ^= 1;   // double-buffered smem: no second barrier needed
        }
    }

    // ---------------- SVD tail: one warp-0 lane per processed batch --------
    __syncthreads();

    if (tid >= cnt) return;

    const int myb = start + tid;

    float tot[16];
    #pragma unroll
    for (int k = 0; k < 16; k++) tot[k] = svd_sm[tid][k];

    float W  = tot[0];
    float d  = W + EPS_W;
    float id = __fdividef(1.0f, d);
    float coef = (2.0f * d - W) * id * id * id;

    float Sx[3] = {tot[1], tot[2], tot[3]};
    float Sy[3] = {tot[4], tot[5], tot[6]};
    float H[3][3];
    #pragma unroll
    for (int i = 0; i < 3; i++)
        #pragma unroll
        for (int j = 0; j < 3; j++)
            H[i][j] = tot[7 + i * 3 + j] * id - Sx[i] * Sy[j] * coef;

    float src_c[3] = {Sx[0] * id, Sx[1] * id, Sx[2] * id};
    float tgt_c[3] = {Sy[0] * id, Sy[1] * id, Sy[2] * id};

    float A[3][3];
    #pragma unroll
    for (int i = 0; i < 3; i++)
        #pragma unroll
        for (int j = 0; j < 3; j++) {
            float s = 0.0f;
            #pragma unroll
            for (int k = 0; k < 3; k++) s += H[k][i] * H[k][j];
            A[i][j] = s;
        }

    float V[3][3] = {{1, 0, 0}, {0, 1, 0}, {0, 0, 1}};

    #pragma unroll 1
    for (int sweep = 0; sweep < 4; sweep++) {
        #pragma unroll
        for (int pair = 0; pair < 3; pair++) {
            const int p2 = (pair == 2) ? 1 : 0;
            const int q2 = (pair == 0) ? 1 : 2;
            float apq = A[p2][q2];
            if (fabsf(apq) > 1e-30f) {
                float tau = __fdividef(A[q2][q2] - A[p2][p2], 2.0f * apq);
                tau = fminf(fmaxf(tau, -1e18f), 1e18f);   // overflow-safe
                float h   = 1.0f + tau * tau;
                float sq  = h * rsqrtf(h);                // sqrt(1+tau^2)
                float tt  = __fdividef(copysignf(1.0f, tau),
                                       fabsf(tau) + sq);
                float cc  = rsqrtf(1.0f + tt * tt);
                float ss  = tt * cc;
                #pragma unroll
                for (int k = 0; k < 3; k++) {
                    float akp = A[k][p2], akq = A[k][q2];
                    A[k][p2] = cc * akp - ss * akq;
                    A[k][q2] = ss * akp + cc * akq;
                }
                #pragma unroll
                for (int k = 0; k < 3; k++) {
                    float apk = A[p2][k], aqk = A[q2][k];
                    A[p2][k] = cc * apk - ss * aqk;
                    A[q2][k] = ss * apk + cc * aqk;
                }
                #pragma unroll
                for (int k = 0; k < 3; k++) {
                    float vkp = V[k][p2], vkq = V[k][q2];
                    V[k][p2] = cc * vkp - ss * vkq;
                    V[k][q2] = ss * vkp + cc * vkq;
                }
            }
        }
    }

    float eig[3] = {A[0][0], A[1][1], A[2][2]};
    int i0 = 0, i1 = 1, i2 = 2, tmpi;
    if (eig[i0] < eig[i1]) { tmpi = i0; i0 = i1; i1 = tmpi; }
    if (eig[i0] < eig[i2]) { tmpi = i0; i0 = i2; i2 = tmpi; }
    if (eig[i1] < eig[i2]) { tmpi = i1; i1 = i2; i2 = tmpi; }

    float v0[3] = {V[0][i0], V[1][i0], V[2][i0]};
    float v1[3] = {V[0][i1], V[1][i1], V[2][i1]};
    float v2[3] = {v0[1] * v1[2] - v0[2] * v1[1],
                   v0[2] * v1[0] - v0[0] * v1[2],
                   v0[0] * v1[1] - v0[1] * v1[0]};

    float u0[3], u1[3], u2[3];
    #pragma unroll
    for (int i = 0; i < 3; i++)
        u0[i] = H[i][0] * v0[0] + H[i][1] * v0[1] + H[i][2] * v0[2];
    float rn0 = rsqrtf(u0[0] * u0[0] + u0[1] * u0[1] + u0[2] * u0[2] + 1e-30f);
    u0[0] *= rn0; u0[1] *= rn0; u0[2] *= rn0;

    #pragma unroll
    for (int i = 0; i < 3; i++)
        u1[i] = H[i][0] * v1[0] + H[i][1] * v1[1] + H[i][2] * v1[2];
    float dp = u1[0] * u0[0] + u1[1] * u0[1] + u1[2] * u0[2];
    u1[0] -= dp * u0[0]; u1[1] -= dp * u0[1]; u1[2] -= dp * u0[2];
    float rn1 = rsqrtf(u1[0] * u1[0] + u1[1] * u1[1] + u1[2] * u1[2] + 1e-30f);
    u1[0] *= rn1; u1[1] *= rn1; u1[2] *= rn1;

    u2[0] = u0[1] * u1[2] - u0[2] * u1[1];
    u2[1] = u0[2] * u1[0] - u0[0] * u1[2];
    u2[2] = u0[0] * u1[1] - u0[1] * u1[0];

    float R[3][3];
    #pragma unroll
    for (int i = 0; i < 3; i++)
        #pragma unroll
        for (int j = 0; j < 3; j++)
            R[i][j] = v0[i] * u0[j] + v1[i] * u1[j] + v2[i] * u2[j];

    float t[3];
    #pragma unroll
    for (int i = 0; i < 3; i++)
        t[i] = tgt_c[i] - (R[i][0] * src_c[0] + R[i][1] * src_c[1] + R[i][2] * src_c[2]);

    float* Rb = Rout + (size_t)myb * 9;
    #pragma unroll
    for (int i = 0; i < 3; i++)
        #pragma unroll
        for (int j = 0; j < 3; j++)
            Rb[i * 3 + j] = R[i][j];
    float* tb = tout + (size_t)myb * 3;
    tb[0] = t[0]; tb[1] = t[1]; tb[2] = t[2];
}

extern "C" void kernel_launch(void* const* d_in, const int* in_sizes, int n_in,
                              void* d_out, int out_size)
{
    const float* src = (const float*)d_in[0];
    const float* tgt = (const float*)d_in[1];
    const float* w   = (const float*)d_in[2];
    int B = in_sizes[2] / NPTS;
    float* Rout = (float*)d_out;
    float* tout = Rout + (size_t)B * 9;
    int grid = (B < RED_BLOCKS) ? B : RED_BLOCKS;
    wproc_fused<<<grid, 256>>>(src, tgt, w, Rout, tout, B);
}

// round 15
// speedup vs baseline: 1.4885x; 1.0102x over previous
#include <cuda_runtime.h>

#define NPTS 1024
#define WEIGHT_THRESH 0.5f
#define EPS_W 1e-5f
#define RED_BLOCKS 444   // 3 resident blocks per SM on 148 SMs
#define MAX_ITERS 16     // >= ceil(4096/444)+1 = 10 with margin

// ---------------------------------------------------------------------------
// Fused persistent kernel, contiguous batch ranges, BARRIER-FREE hot loop:
// each warp reduces to 16 partials and stores them to its own smem slot;
// the 8-way cross-warp sum is deferred to the SVD tail. One __syncthreads()
// total. SIMT SVD tail: one warp-0 lane per processed batch.
// ---------------------------------------------------------------------------
__global__ __launch_bounds__(256, 3)
void wproc_fused(const float* __restrict__ src,
                 const float* __restrict__ tgt,
                 const float* __restrict__ wgt,
                 float* __restrict__ Rout,
                 float* __restrict__ tout,
                 int B)
{
    const int tid  = threadIdx.x;
    const int warp = tid >> 5, lane = tid & 31;

    // contiguous partition: first `rem` blocks get base+1 batches
    const int grid  = gridDim.x;
    const int base  = B / grid;
    const int rem   = B - base * grid;
    const int cnt   = base + (blockIdx.x < rem ? 1 : 0);
    const int start = blockIdx.x * base + min((int)blockIdx.x, rem);

    // per-iteration, per-warp partials: [iter][warp][16]
    __shared__ float svd_sm[MAX_ITERS][8][16];

    if (cnt > 0) {
        int b = start;

        float4 wv, a0, a1, a2, c0, c1, c2;
        {
            const float4* s4 = (const float4*)(src + (size_t)b * NPTS * 3);
            const float4* t4 = (const float4*)(tgt + (size_t)b * NPTS * 3);
            const float4* w4 = (const float4*)(wgt + (size_t)b * NPTS);
            wv = w4[tid];
            a0 = s4[3 * tid + 0]; a1 = s4[3 * tid + 1]; a2 = s4[3 * tid + 2];
            c0 = t4[3 * tid + 0]; c1 = t4[3 * tid + 1]; c2 = t4[3 * tid + 2];
        }

        int it = 0;
        while (true) {
            const int bn = b + 1;
            const bool has_next = (it + 1 < cnt);

            // Prefetch next (sequential) batch while reducing current
            float4 nwv, na0, na1, na2, nc0, nc1, nc2;
            if (has_next) {
                const float4* s4 = (const float4*)(src + (size_t)bn * NPTS * 3);
                const float4* t4 = (const float4*)(tgt + (size_t)bn * NPTS * 3);
                const float4* w4 = (const float4*)(wgt + (size_t)bn * NPTS);
                nwv = w4[tid];
                na0 = s4[3 * tid + 0]; na1 = s4[3 * tid + 1]; na2 = s4[3 * tid + 2];
                nc0 = t4[3 * tid + 0]; nc1 = t4[3 * tid + 1]; nc2 = t4[3 * tid + 2];
            }

            float ws[4];
            ws[0] = (wv.x < WEIGHT_THRESH) ? 0.0f : wv.x;
            ws[1] = (wv.y < WEIGHT_THRESH) ? 0.0f : wv.y;
            ws[2] = (wv.z < WEIGHT_THRESH) ? 0.0f : wv.z;
            ws[3] = (wv.w < WEIGHT_THRESH) ? 0.0f : wv.w;

            float px[4][3] = {{a0.x, a0.y, a0.z},
                              {a0.w, a1.x, a1.y},
                              {a1.z, a1.w, a2.x},
                              {a2.y, a2.z, a2.w}};
            float py[4][3] = {{c0.x, c0.y, c0.z},
                              {c0.w, c1.x, c1.y},
                              {c1.z, c1.w, c2.x},
                              {c2.y, c2.z, c2.w}};

            float acc[16];
            #pragma unroll
            for (int k = 0; k < 16; k++) acc[k] = 0.0f;

            #pragma unroll
            for (int k = 0; k < 4; k++) {
                float w = ws[k];
                float x0 = px[k][0], x1 = px[k][1], x2 = px[k][2];
                float y0 = py[k][0], y1 = py[k][1], y2 = py[k][2];
                acc[0] += w;
                acc[1] += w * x0;  acc[2] += w * x1;  acc[3] += w * x2;
                float wy0 = w * y0, wy1 = w * y1, wy2 = w * y2;
                acc[4] += wy0;     acc[5] += wy1;     acc[6] += wy2;
                acc[7]  += x0 * wy0;  acc[8]  += x0 * wy1;  acc[9]  += x0 * wy2;
                acc[10] += x1 * wy0;  acc[11] += x1 * wy1;  acc[12] += x1 * wy2;
                acc[13] += x2 * wy0;  acc[14] += x2 * wy1;  acc[15] += x2 * wy2;
            }

            // ---- reduce-scatter butterfly (warp-local) ----
            {
                bool hi = (lane & 16) != 0;
                #pragma unroll
                for (int j = 0; j < 8; j++) {
                    float send = hi ? acc[j] : acc[j + 8];
                    float keep = hi ? acc[j + 8] : acc[j];
                    acc[j] = keep + __shfl_xor_sync(0xffffffffu, send, 16);
                }
            }
            {
                bool hi = (lane & 8) != 0;
                #pragma unroll
                for (int j = 0; j < 4; j++) {
                    float send = hi ? acc[j] : acc[j + 4];
                    float keep = hi ? acc[j + 4] : acc[j];
                    acc[j] = keep + __shfl_xor_sync(0xffffffffu, send, 8);
                }
            }
            {
                bool hi = (lane & 4) != 0;
                #pragma unroll
                for (int j = 0; j < 2; j++) {
                    float send = hi ? acc[j] : acc[j + 2];
                    float keep = hi ? acc[j + 2] : acc[j];
                    acc[j] = keep + __shfl_xor_sync(0xffffffffu, send, 4);
                }
            }
            {
                bool hi = (lane & 2) != 0;
                float send = hi ? acc[0] : acc[1];
                float keep = hi ? acc[1] : acc[0];
                acc[0] = keep + __shfl_xor_sync(0xffffffffu, send, 2);
            }
            acc[0] += __shfl_xor_sync(0xffffffffu, acc[0], 1);

            // warp-local store of this warp's 16 partials — NO barrier
            const int accIdx = (lane >> 1) & 15;
            if ((lane & 1) == 0)
                svd_sm[it][warp][accIdx] = acc[0];

            if (!has_next) break;
            wv = nwv; a0 = na0; a1 = na1; a2 = na2; c0 = nc0; c1 = nc1; c2 = nc2;
            b = bn;
            it++;
        }
    }

    // -------- single barrier, then SVD tail: lane t owns batch start+t -----
    __syncthreads();

    if (tid >= cnt) return;

    const int myb = start + tid;

    // 8-way cross-warp sum (deferred from the loop)
    float tot[16];
    #pragma unroll
    for (int k = 0; k < 16; k++) {
        float s = 0.0f;
        #pragma unroll
        for (int w = 0; w < 8; w++) s += svd_sm[tid][w][k];
        tot[k] = s;
    }

    float W  = tot[0];
    float d  = W + EPS_W;
    float id = __fdividef(1.0f, d);
    float coef = (2.0f * d - W) * id * id * id;

    float Sx[3] = {tot[1], tot[2], tot[3]};
    float Sy[3] = {tot[4], tot[5], tot[6]};
    float H[3][3];
    #pragma unroll
    for (int i = 0; i < 3; i++)
        #pragma unroll
        for (int j = 0; j < 3; j++)
            H[i][j] = tot[7 + i * 3 + j] * id - Sx[i] * Sy[j] * coef;

    float src_c[3] = {Sx[0] * id, Sx[1] * id, Sx[2] * id};
    float tgt_c[3] = {Sy[0] * id, Sy[1] * id, Sy[2] * id};

    float A[3][3];
    #pragma unroll
    for (int i = 0; i < 3; i++)
        #pragma unroll
        for (int j = 0; j < 3; j++) {
            float s = 0.0f;
            #pragma unroll
            for (int k = 0; k < 3; k++) s += H[k][i] * H[k][j];
            A[i][j] = s;
        }

    float V[3][3] = {{1, 0, 0}, {0, 1, 0}, {0, 0, 1}};

    #pragma unroll 1
    for (int sweep = 0; sweep < 4; sweep++) {
        #pragma unroll
        for (int pair = 0; pair < 3; pair++) {
            const int p2 = (pair == 2) ? 1 : 0;
            const int q2 = (pair == 0) ? 1 : 2;
            float apq = A[p2][q2];
            if (fabsf(apq) > 1e-30f) {
                float tau = __fdividef(A[q2][q2] - A[p2][p2], 2.0f * apq);
                tau = fminf(fmaxf(tau, -1e18f), 1e18f);   // overflow-safe
                float h   = 1.0f + tau * tau;
                float sq  = h * rsqrtf(h);                // sqrt(1+tau^2)
                float tt  = __fdividef(copysignf(1.0f, tau),
                                       fabsf(tau) + sq);
                float cc  = rsqrtf(1.0f + tt * tt);
                float ss  = tt * cc;
                #pragma unroll
                for (int k = 0; k < 3; k++) {
                    float akp = A[k][p2], akq = A[k][q2];
                    A[k][p2] = cc * akp - ss * akq;
                    A[k][q2] = ss * akp + cc * akq;
                }
                #pragma unroll
                for (int k = 0; k < 3; k++) {
                    float apk = A[p2][k], aqk = A[q2][k];
                    A[p2][k] = cc * apk - ss * aqk;
                    A[q2][k] = ss * apk + cc * aqk;
                }
                #pragma unroll
                for (int k = 0; k < 3; k++) {
                    float vkp = V[k][p2], vkq = V[k][q2];
                    V[k][p2] = cc * vkp - ss * vkq;
                    V[k][q2] = ss * vkp + cc * vkq;
                }
            }
        }
    }

    float eig[3] = {A[0][0], A[1][1], A[2][2]};
    int i0 = 0, i1 = 1, i2 = 2, tmpi;
    if (eig[i0] < eig[i1]) { tmpi = i0; i0 = i1; i1 = tmpi; }
    if (eig[i0] < eig[i2]) { tmpi = i0; i0 = i2; i2 = tmpi; }
    if (eig[i1] < eig[i2]) { tmpi = i1; i1 = i2; i2 = tmpi; }

    float v0[3] = {V[0][i0], V[1][i0], V[2][i0]};
    float v1[3] = {V[0][i1], V[1][i1], V[2][i1]};
    float v2[3] = {v0[1] * v1[2] - v0[2] * v1[1],
                   v0[2] * v1[0] - v0[0] * v1[2],
                   v0[0] * v1[1] - v0[1] * v1[0]};

    float u0[3], u1[3], u2[3];
    #pragma unroll
    for (int i = 0; i < 3; i++)
        u0[i] = H[i][0] * v0[0] + H[i][1] * v0[1] + H[i][2] * v0[2];
    float rn0 = rsqrtf(u0[0] * u0[0] + u0[1] * u0[1] + u0[2] * u0[2] + 1e-30f);
    u0[0] *= rn0; u0[1] *= rn0; u0[2] *= rn0;

    #pragma unroll
    for (int i = 0; i < 3; i++)
        u1[i] = H[i][0] * v1[0] + H[i][1] * v1[1] + H[i][2] * v1[2];
    float dp = u1[0] * u0[0] + u1[1] * u0[1] + u1[2] * u0[2];
    u1[0] -= dp * u0[0]; u1[1] -= dp * u0[1]; u1[2] -= dp * u0[2];
    float rn1 = rsqrtf(u1[0] * u1[0] + u1[1] * u1[1] + u1[2] * u1[2] + 1e-30f);
    u1[0] *= rn1; u1[1] *= rn1; u1[2] *= rn1;

    u2[0] = u0[1] * u1[2] - u0[2] * u1[1];
    u2[1] = u0[2] * u1[0] - u0[0] * u1[2];
    u2[2] = u0[0] * u1[1] - u0[1] * u1[0];

    float R[3][3];
    #pragma unroll
    for (int i = 0; i < 3; i++)
        #pragma unroll
        for (int j = 0; j < 3; j++)
            R[i][j] = v0[i] * u0[j] + v1[i] * u1[j] + v2[i] * u2[j];

    float t[3];
    #pragma unroll
    for (int i = 0; i < 3; i++)
        t[i] = tgt_c[i] - (R[i][0] * src_c[0] + R[i][1] * src_c[1] + R[i][2] * src_c[2]);

    float* Rb = Rout + (size_t)myb * 9;
    #pragma unroll
    for (int i = 0; i < 3; i++)
        #pragma unroll
        for (int j = 0; j < 3; j++)
            Rb[i * 3 + j] = R[i][j];
    float* tb = tout + (size_t)myb * 3;
    tb[0] = t[0]; tb[1] = t[1]; tb[2] = t[2];
}

extern "C" void kernel_launch(void* const* d_in, const int* in_sizes, int n_in,
                              void* d_out, int out_size)
{
    const float* src = (const float*)d_in[0];
    const float* tgt = (const float*)d_in[1];
    const float* w   = (const float*)d_in[2];
    int B = in_sizes[2] / NPTS;
    float* Rout = (float*)d_out;
    float* tout = Rout + (size_t)B * 9;
    int grid = (B < RED_BLOCKS) ? B : RED_BLOCKS;
    wproc_fused<<<grid, 256>>>(src, tgt, w, Rout, tout, B);
}

// round 16
// speedup vs baseline: 1.5156x; 1.0182x over previous
#include <cuda_runtime.h>

#define NPTS 1024
#define WEIGHT_THRESH 0.5f
#define EPS_W 1e-5f
#define RED_BLOCKS 410   // balanced: 406 blocks x 10 iters, 4 x 9 (B=4096)
#define MAX_ITERS 32     // >= ceil(B / RED_BLOCKS)

// ---------------------------------------------------------------------------
// Fused persistent kernel (proven R8 structure): strided batch assignment,
// register prefetch of the next batch, reduce-scatter butterfly, double-
// buffered smem, SIMT SVD tail (one warp-0 lane per processed batch).
// ---------------------------------------------------------------------------
__global__ __launch_bounds__(256, 3)
void wproc_fused(const float* __restrict__ src,
                 const float* __restrict__ tgt,
                 const float* __restrict__ wgt,
                 float* __restrict__ Rout,
                 float* __restrict__ tout,
                 int B)
{
    const int tid    = threadIdx.x;
    const int stride = gridDim.x;
    const int warp   = tid >> 5, lane = tid & 31;

    __shared__ float sm[2][8 * 16];
    __shared__ float svd_sm[MAX_ITERS][16];

    int b = blockIdx.x;
    if (b < B) {
        float4 wv, a0, a1, a2, c0, c1, c2;
        {
            const float4* s4 = (const float4*)(src + (size_t)b * NPTS * 3);
            const float4* t4 = (const float4*)(tgt + (size_t)b * NPTS * 3);
            const float4* w4 = (const float4*)(wgt + (size_t)b * NPTS);
            wv = w4[tid];
            a0 = s4[3 * tid + 0]; a1 = s4[3 * tid + 1]; a2 = s4[3 * tid + 2];
            c0 = t4[3 * tid + 0]; c1 = t4[3 * tid + 1]; c2 = t4[3 * tid + 2];
        }

        int p = 0;
        int it = 0;
        while (true) {
            const int bn = b + stride;
            const bool has_next = (bn < B);

            // Prefetch next batch (loads in flight while we reduce current)
            float4 nwv, na0, na1, na2, nc0, nc1, nc2;
            if (has_next) {
                const float4* s4 = (const float4*)(src + (size_t)bn * NPTS * 3);
                const float4* t4 = (const float4*)(tgt + (size_t)bn * NPTS * 3);
                const float4* w4 = (const float4*)(wgt + (size_t)bn * NPTS);
                nwv = w4[tid];
                na0 = s4[3 * tid + 0]; na1 = s4[3 * tid + 1]; na2 = s4[3 * tid + 2];
                nc0 = t4[3 * tid + 0]; nc1 = t4[3 * tid + 1]; nc2 = t4[3 * tid + 2];
            }

            float ws[4];
            ws[0] = (wv.x < WEIGHT_THRESH) ? 0.0f : wv.x;
            ws[1] = (wv.y < WEIGHT_THRESH) ? 0.0f : wv.y;
            ws[2] = (wv.z < WEIGHT_THRESH) ? 0.0f : wv.z;
            ws[3] = (wv.w < WEIGHT_THRESH) ? 0.0f : wv.w;

            float px[4][3] = {{a0.x, a0.y, a0.z},
                              {a0.w, a1.x, a1.y},
                              {a1.z, a1.w, a2.x},
                              {a2.y, a2.z, a2.w}};
            float py[4][3] = {{c0.x, c0.y, c0.z},
                              {c0.w, c1.x, c1.y},
                              {c1.z, c1.w, c2.x},
                              {c2.y, c2.z, c2.w}};

            float acc[16];
            #pragma unroll
            for (int k = 0; k < 16; k++) acc[k] = 0.0f;

            #pragma unroll
            for (int k = 0; k < 4; k++) {
                float w = ws[k];
                float x0 = px[k][0], x1 = px[k][1], x2 = px[k][2];
                float y0 = py[k][0], y1 = py[k][1], y2 = py[k][2];
                acc[0] += w;
                acc[1] += w * x0;  acc[2] += w * x1;  acc[3] += w * x2;
                float wy0 = w * y0, wy1 = w * y1, wy2 = w * y2;
                acc[4] += wy0;     acc[5] += wy1;     acc[6] += wy2;
                acc[7]  += x0 * wy0;  acc[8]  += x0 * wy1;  acc[9]  += x0 * wy2;
                acc[10] += x1 * wy0;  acc[11] += x1 * wy1;  acc[12] += x1 * wy2;
                acc[13] += x2 * wy0;  acc[14] += x2 * wy1;  acc[15] += x2 * wy2;
            }

            // ---- reduce-scatter butterfly: halve active set each round ----
            {
                bool hi = (lane & 16) != 0;
                #pragma unroll
                for (int j = 0; j < 8; j++) {
                    float send = hi ? acc[j] : acc[j + 8];
                    float keep = hi ? acc[j + 8] : acc[j];
                    acc[j] = keep + __shfl_xor_sync(0xffffffffu, send, 16);
                }
            }
            {
                bool hi = (lane & 8) != 0;
                #pragma unroll
                for (int j = 0; j < 4; j++) {
                    float send = hi ? acc[j] : acc[j + 4];
                    float keep = hi ? acc[j + 4] : acc[j];
                    acc[j] = keep + __shfl_xor_sync(0xffffffffu, send, 8);
                }
            }
            {
                bool hi = (lane & 4) != 0;
                #pragma unroll
                for (int j = 0; j < 2; j++) {
                    float send = hi ? acc[j] : acc[j + 2];
                    float keep = hi ? acc[j + 2] : acc[j];
                    acc[j] = keep + __shfl_xor_sync(0xffffffffu, send, 4);
                }
            }
            {
                bool hi = (lane & 2) != 0;
                float send = hi ? acc[0] : acc[1];
                float keep = hi ? acc[1] : acc[0];
                acc[0] = keep + __shfl_xor_sync(0xffffffffu, send, 2);
            }
            acc[0] += __shfl_xor_sync(0xffffffffu, acc[0], 1);

            const int accIdx = (lane >> 1) & 15;
            if ((lane & 1) == 0)
                sm[p][warp * 16 + accIdx] = acc[0];
            __syncthreads();
            if (tid < 16) {
                float s = 0.0f;
                #pragma unroll
                for (int w = 0; w < 8; w++) s += sm[p][w * 16 + tid];
                svd_sm[it][tid] = s;
            }

            if (!has_next) break;
            wv = nwv; a0 = na0; a1 = na1; a2 = na2; c0 = nc0; c1 = nc1; c2 = nc2;
            b = bn;
            it++;
            p ^= 1;   // double-buffered smem: no second barrier needed
        }
    }

    // ---------------- SVD tail: warp-0 lanes, one batch each ---------------
    __syncthreads();

    int niter = 0;
    if (blockIdx.x < B)
        niter = (B - blockIdx.x + stride - 1) / stride;

    if (tid >= niter) return;   // only warp-0 lanes 0..niter-1 continue

    const int myb = blockIdx.x + tid * stride;

    float tot[16];
    #pragma unroll
    for (int k = 0; k < 16; k++) tot[k] = svd_sm[tid][k];

    float W  = tot[0];
    float d  = W + EPS_W;
    float id = __fdividef(1.0f, d);
    float coef = (2.0f * d - W) * id * id * id;

    float Sx[3] = {tot[1], tot[2], tot[3]};
    float Sy[3] = {tot[4], tot[5], tot[6]};
    float H[3][3];
    #pragma unroll
    for (int i = 0; i < 3; i++)
        #pragma unroll
        for (int j = 0; j < 3; j++)
            H[i][j] = tot[7 + i * 3 + j] * id - Sx[i] * Sy[j] * coef;

    float src_c[3] = {Sx[0] * id, Sx[1] * id, Sx[2] * id};
    float tgt_c[3] = {Sy[0] * id, Sy[1] * id, Sy[2] * id};

    // A = H^T H
    float A[3][3];
    #pragma unroll
    for (int i = 0; i < 3; i++)
        #pragma unroll
        for (int j = 0; j < 3; j++) {
            float s = 0.0f;
            #pragma unroll
            for (int k = 0; k < 3; k++) s += H[k][i] * H[k][j];
            A[i][j] = s;
        }

    float V[3][3] = {{1, 0, 0}, {0, 1, 0}, {0, 0, 1}};

    #pragma unroll 1
    for (int sweep = 0; sweep < 4; sweep++) {
        #pragma unroll
        for (int pair = 0; pair < 3; pair++) {
            const int p2 = (pair == 2) ? 1 : 0;
            const int q2 = (pair == 0) ? 1 : 2;
            float apq = A[p2][q2];
            if (fabsf(apq) > 1e-30f) {
                float tau = __fdividef(A[q2][q2] - A[p2][p2], 2.0f * apq);
                tau = fminf(fmaxf(tau, -1e18f), 1e18f);   // overflow-safe
                float h   = 1.0f + tau * tau;
                float sq  = h * rsqrtf(h);                // sqrt(1+tau^2)
                float tt  = __fdividef(copysignf(1.0f, tau),
                                       fabsf(tau) + sq);
                float cc  = rsqrtf(1.0f + tt * tt);
                float ss  = tt * cc;
                #pragma unroll
                for (int k = 0; k < 3; k++) {
                    float akp = A[k][p2], akq = A[k][q2];
                    A[k][p2] = cc * akp - ss * akq;
                    A[k][q2] = ss * akp + cc * akq;
                }
                #pragma unroll
                for (int k = 0; k < 3; k++) {
                    float apk = A[p2][k], aqk = A[q2][k];
                    A[p2][k] = cc * apk - ss * aqk;
                    A[q2][k] = ss * apk + cc * aqk;
                }
                #pragma unroll
                for (int k = 0; k < 3; k++) {
                    float vkp = V[k][p2], vkq = V[k][q2];
                    V[k][p2] = cc * vkp - ss * vkq;
                    V[k][q2] = ss * vkp + cc * vkq;
                }
            }
        }
    }

    float eig[3] = {A[0][0], A[1][1], A[2][2]};
    int i0 = 0, i1 = 1, i2 = 2, tmpi;
    if (eig[i0] < eig[i1]) { tmpi = i0; i0 = i1; i1 = tmpi; }
    if (eig[i0] < eig[i2]) { tmpi = i0; i0 = i2; i2 = tmpi; }
    if (eig[i1] < eig[i2]) { tmpi = i1; i1 = i2; i2 = tmpi; }

    float v0[3] = {V[0][i0], V[1][i0], V[2][i0]};
    float v1[3] = {V[0][i1], V[1][i1], V[2][i1]};
    float v2[3] = {v0[1] * v1[2] - v0[2] * v1[1],
                   v0[2] * v1[0] - v0[0] * v1[2],
                   v0[0] * v1[1] - v0[1] * v1[0]};

    float u0[3], u1[3], u2[3];
    #pragma unroll
    for (int i = 0; i < 3; i++)
        u0[i] = H[i][0] * v0[0] + H[i][1] * v0[1] + H[i][2] * v0[2];
    float rn0 = rsqrtf(u0[0] * u0[0] + u0[1] * u0[1] + u0[2] * u0[2] + 1e-30f);
    u0[0] *= rn0; u0[1] *= rn0; u0[2] *= rn0;

    #pragma unroll
    for (int i = 0; i < 3; i++)
        u1[i] = H[i][0] * v1[0] + H[i][1] * v1[1] + H[i][2] * v1[2];
    float dp = u1[0] * u0[0] + u1[1] * u0[1] + u1[2] * u0[2];
    u1[0] -= dp * u0[0]; u1[1] -= dp * u0[1]; u1[2] -= dp * u0[2];
    float rn1 = rsqrtf(u1[0] * u1[0] + u1[1] * u1[1] + u1[2] * u1[2] + 1e-30f);
    u1[0] *= rn1; u1[1] *= rn1; u1[2] *= rn1;

    u2[0] = u0[1] * u1[2] - u0[2] * u1[1];
    u2[1] = u0[2] * u1[0] - u0[0] * u1[2];
    u2[2] = u0[0] * u1[1] - u0[1] * u1[0];

    // R = V * U^T
    float R[3][3];
    #pragma unroll
    for (int i = 0; i < 3; i++)
        #pragma unroll
        for (int j = 0; j < 3; j++)
            R[i][j] = v0[i] * u0[j] + v1[i] * u1[j] + v2[i] * u2[j];

    float t[3];
    #pragma unroll
    for (int i = 0; i < 3; i++)
        t[i] = tgt_c[i] - (R[i][0] * src_c[0] + R[i][1] * src_c[1] + R[i][2] * src_c[2]);

    float* Rb = Rout + (size_t)myb * 9;
    #pragma unroll
    for (int i = 0; i < 3; i++)
        #pragma unroll
        for (int j = 0; j < 3; j++)
            Rb[i * 3 + j] = R[i][j];
    float* tb = tout + (size_t)myb * 3;
    tb[0] = t[0]; tb[1] = t[1]; tb[2] = t[2];
}

extern "C" void kernel_launch(void* const* d_in, const int* in_sizes, int n_in,
                              void* d_out, int out_size)
{
    const float* src = (const float*)d_in[0];
    const float* tgt = (const float*)d_in[1];
    const float* w   = (const float*)d_in[2];
    int B = in_sizes[2] / NPTS;
    float* Rout = (float*)d_out;
    float* tout = Rout + (size_t)B * 9;
    int grid = (B < RED_BLOCKS) ? B : RED_BLOCKS;
    wproc_fused<<<grid, 256>>>(src, tgt, w, Rout, tout, B);
}